// round 14
// baseline (speedup 1.0000x reference)
#include <cuda_runtime.h>
#include <cuda_fp16.h>
#include <math.h>

#define NN   100000
#define NE   1600000
#define INF  64
#define HIDD 128
#define NCLS 10
#define NCP  12
#define SB   512
#define NBS  ((NN + SB - 1) / SB)    // 196 scan blocks
#define FULL 0xffffffffu

// packed f32x2 helpers
__device__ __forceinline__ unsigned long long f2pk(float lo, float hi) {
    unsigned long long r;
    asm("mov.b64 %0, {%1, %2};" : "=l"(r) : "f"(lo), "f"(hi));
    return r;
}
__device__ __forceinline__ void ffma2(unsigned long long& d,
                                      unsigned long long a,
                                      unsigned long long b) {
    asm("fma.rn.f32x2 %0, %1, %2, %0;" : "+l"(d) : "l"(a), "l"(b));
}
__device__ __forceinline__ float2 f2unpk(unsigned long long v) {
    float lo, hi;
    asm("mov.b64 {%0, %1}, %2;" : "=f"(lo), "=f"(hi) : "l"(v));
    return make_float2(lo, hi);
}

// per-warp dtype sniff: int64 edge_index => odd 32-bit words of first 32 elems all 0
__device__ __forceinline__ bool sniff_is64(const void* ei_raw, int lane) {
    unsigned int odd = ((const unsigned int*)ei_raw)[lane * 2 + 1];
    return __ballot_sync(FULL, odd != 0u) == 0u;
}

// ---------------- scratch (no allocations allowed) ----------------
// NOTE: pipeline is self-restoring — g_cnt and g_done return to 0 by the end of
// every kernel_launch invocation (module-load state is zero), so no init pass.
__device__ int   g_done;
__device__ int   g_cnt[NN];
__device__ int   g_offs[NN];          // block-local exclusive scan (SB-wide blocks)
__device__ int   g_bsum[NBS];
__device__ int   g_bpre[NBS];
__device__ float g_dinv[NN];
__device__ unsigned short g_rank[NE]; // 3.2 MB : edge's rank within its dest bucket
__device__ int   g_msrc[NE];          // 6.4 MB : CSR src per slot
__device__ __half2 g_xh[NN * 32];     // 12.8 MB : xs = dinv*x in half
__device__ float4 g_agg1[NN * (INF / 4)];   // 25.6 MB
__device__ float g_t2s[NN * NCP];           // 4.8 MB : dinv*(h@W2), stride 12

// ---------------- kernels ----------------

// degree histogram + rank ticket (returning atomic; rank = position in bucket)
__global__ void k_degree(const void* __restrict__ ei_raw) {
    int e = blockIdx.x * blockDim.x + threadIdx.x;
    bool is64 = sniff_is64(ei_raw, threadIdx.x & 31);
    if (e >= NE) return;
    int c;
    if (is64) c = (int)((const long long*)ei_raw)[NE + e];
    else      c = ((const int*)ei_raw)[NE + e];
    c = min(max(c, 0), NN - 1);
    int t = atomicAdd(&g_cnt[c], 1);
    g_rank[e] = (unsigned short)t;
}

// fused scan: block-local exclusive scan + dinv + out-zero; last block scans
// block sums and self-resets g_done
__global__ void k_scan(float* __restrict__ out) {
    __shared__ int s[SB];
    __shared__ int isLast;
    int tid = threadIdx.x;
    int i = blockIdx.x * SB + tid;
    if (blockIdx.x == 0 && tid < NCLS) out[tid] = 0.0f;
    int v = (i < NN) ? g_cnt[i] : 0;
    if (i < NN) g_dinv[i] = rsqrtf((float)(v + 1));
    s[tid] = v;
    __syncthreads();
    #pragma unroll
    for (int st = 1; st < SB; st <<= 1) {
        int t = (tid >= st) ? s[tid - st] : 0;
        __syncthreads();
        s[tid] += t;
        __syncthreads();
    }
    if (i < NN) g_offs[i] = s[tid] - v;
    if (tid == SB - 1) {
        g_bsum[blockIdx.x] = s[SB - 1];
        __threadfence();
        int t = atomicAdd(&g_done, 1);
        isLast = (t == (int)gridDim.x - 1);
    }
    __syncthreads();
    if (isLast) {
        int v2 = (tid < NBS) ? g_bsum[tid] : 0;
        s[tid] = v2;
        __syncthreads();
        #pragma unroll
        for (int st = 1; st < SB; st <<= 1) {
            int t = (tid >= st) ? s[tid - st] : 0;
            __syncthreads();
            s[tid] += t;
            __syncthreads();
        }
        if (tid < NBS) g_bpre[tid] = s[tid] - v2;
        if (tid == 0) g_done = 0;        // self-restore for next replay
    }
}

// fused: CSR fill via precomputed rank (NO atomics) + xs = dinv*x -> half
__global__ void k_fillx(const void* __restrict__ ei_raw, const float* __restrict__ x) {
    int i = blockIdx.x * blockDim.x + threadIdx.x;   // NN*32 = 3.2M threads
    bool is64 = sniff_is64(ei_raw, threadIdx.x & 31);
    if (i < NE) {
        int r, c;
        if (is64) {
            const long long* ei = (const long long*)ei_raw;
            r = (int)ei[i];  c = (int)ei[NE + i];
        } else {
            const int* ei = (const int*)ei_raw;
            r = ei[i];       c = ei[NE + i];
        }
        r = min(max(r, 0), NN - 1);
        c = min(max(c, 0), NN - 1);
        int pos = g_offs[c] + g_bpre[c >> 9] + (int)g_rank[i];
        g_msrc[pos] = r;
    }
    if (i < NN * 32) {
        int node = i >> 5;
        float d = g_dinv[node];
        float2 v = ((const float2*)x)[i];
        g_xh[i] = __floats2half2_rn(d * v.x, d * v.y);
    }
}

// layer-1 aggregation: warp per dest node, shfl-chunked meta, MLP=4
__global__ void k_gather1() {
    int wid  = (blockIdx.x * blockDim.x + threadIdx.x) >> 5;
    int lane = threadIdx.x & 31;
    if (wid >= NN) return;
    int d = wid;
    float2 acc = __half22float2(g_xh[d * 32 + lane]);   // self term xs[d]
    float2 acc2 = make_float2(0.f, 0.f);
    int beg = g_offs[d] + g_bpre[d >> 9];
    int deg = g_cnt[d];
    for (int base = 0; base < deg; base += 32) {
        int rem = deg - base;
        int cnt = rem < 32 ? rem : 32;
        int m = (lane < cnt) ? g_msrc[beg + base + lane] : 0;
        int j = 0;
        for (; j + 4 <= cnt; j += 4) {
            int s0 = __shfl_sync(FULL, m, j);
            int s1 = __shfl_sync(FULL, m, j + 1);
            int s2 = __shfl_sync(FULL, m, j + 2);
            int s3 = __shfl_sync(FULL, m, j + 3);
            float2 f0 = __half22float2(g_xh[s0 * 32 + lane]);
            float2 f1 = __half22float2(g_xh[s1 * 32 + lane]);
            float2 f2 = __half22float2(g_xh[s2 * 32 + lane]);
            float2 f3 = __half22float2(g_xh[s3 * 32 + lane]);
            acc.x  += f0.x + f1.x;  acc.y  += f0.y + f1.y;
            acc2.x += f2.x + f3.x;  acc2.y += f2.y + f3.y;
        }
        for (; j < cnt; j++) {
            int src = __shfl_sync(FULL, m, j);
            float2 v = __half22float2(g_xh[src * 32 + lane]);
            acc.x += v.x;  acc.y += v.y;
        }
    }
    float dd = g_dinv[d];
    acc.x = (acc.x + acc2.x) * dd;
    acc.y = (acc.y + acc2.y) * dd;
    ((float2*)g_agg1)[d * 32 + lane] = acc;
}

// fused: h = relu(agg1@W1 + b1) [smem only] ; t2s = dinv*(h@W2)
__global__ void k_gemm12(const float* __restrict__ W1, const float* __restrict__ b1,
                         const float* __restrict__ W2) {
    __shared__ float As[64 * 64];        // A tile / then W2 (1280 floats)
    __shared__ float Bs[64 * 132];       // W1 (64x128) / then h tile stride 132
    int tid = threadIdx.x;
    int bnode = blockIdx.x * 64;

    for (int t = tid; t < (64 * 128) / 4; t += 256)
        ((float4*)Bs)[t] = ((const float4*)W1)[t];
    for (int t = tid; t < 64 * 16; t += 256) {
        int lr = t >> 4, q = t & 15;
        int node = bnode + lr;
        float4 v = (node < NN) ? g_agg1[node * 16 + q]
                               : make_float4(0.f, 0.f, 0.f, 0.f);
        ((float4*)As)[t] = v;
    }
    __syncthreads();

    int tx = tid & 31, ty = tid >> 5;
    unsigned long long a01[8], a23[8];
    #pragma unroll
    for (int i = 0; i < 8; i++) { a01[i] = 0ull; a23[i] = 0ull; }

    #pragma unroll 4
    for (int k = 0; k < 64; k++) {
        float4 bb = ((const float4*)Bs)[k * 32 + tx];
        unsigned long long b01 = f2pk(bb.x, bb.y);
        unsigned long long b23 = f2pk(bb.z, bb.w);
        #pragma unroll
        for (int i = 0; i < 8; i++) {
            float a = As[(ty * 8 + i) * 64 + k];
            unsigned long long aa = f2pk(a, a);
            ffma2(a01[i], aa, b01);
            ffma2(a23[i], aa, b23);
        }
    }
    __syncthreads();

    float4 bias = ((const float4*)b1)[tx];
    #pragma unroll
    for (int i = 0; i < 8; i++) {
        float2 p = f2unpk(a01[i]);
        float2 q = f2unpk(a23[i]);
        float* hrow = &Bs[(ty * 8 + i) * 132 + tx * 4];
        hrow[0] = fmaxf(p.x + bias.x, 0.0f);
        hrow[1] = fmaxf(p.y + bias.y, 0.0f);
        hrow[2] = fmaxf(q.x + bias.z, 0.0f);
        hrow[3] = fmaxf(q.y + bias.w, 0.0f);
    }
    for (int t = tid; t < HIDD * NCLS; t += 256) As[t] = W2[t];
    __syncthreads();

    for (int o = tid; o < 64 * NCLS; o += 256) {
        int ln = o / NCLS, c = o - ln * NCLS;
        int node = bnode + ln;
        if (node < NN) {
            const float* h = &Bs[ln * 132];
            float s = 0.0f;
            #pragma unroll 8
            for (int k = 0; k < HIDD; k++) s = fmaf(h[k], As[k * NCLS + c], s);
            g_t2s[node * NCP + c] = g_dinv[node] * s;
        }
    }
}

// fused: layer-2 gather + bias + self + log_softmax + global mean-reduce.
// Also self-restores g_cnt to 0 (so no init pass is needed next replay).
__global__ void k_gather2f(const float* __restrict__ b2, float* __restrict__ out) {
    __shared__ float sacc[NCLS];
    int tid = threadIdx.x;
    if (tid < NCLS) sacc[tid] = 0.0f;
    __syncthreads();
    int wid  = (blockIdx.x * blockDim.x + tid) >> 5;
    int lane = tid & 31;
    if (wid < NN) {
        int d = wid;
        int s = lane / 10;          // 0..2 active
        int c = lane - s * 10;
        float acc = 0.0f, accB = 0.0f;
        int beg = g_offs[d] + g_bpre[d >> 9];
        int deg = g_cnt[d];
        if (lane == 0) g_cnt[d] = 0;     // self-restore after last read
        for (int base = 0; base < deg; base += 32) {
            int rem = deg - base;
            int cnt = rem < 32 ? rem : 32;
            int m = (lane < cnt) ? g_msrc[beg + base + lane] : 0;
            int iters = (cnt + 2) / 3;
            int jj = 0;
            for (; jj + 2 <= iters; jj += 2) {
                int j0 = jj * 3 + s;
                int j1 = j0 + 3;
                int s0 = __shfl_sync(FULL, m, j0 < 31 ? j0 : 31);
                int s1 = __shfl_sync(FULL, m, j1 < 31 ? j1 : 31);
                float t0 = 0.f, t1 = 0.f;
                if (s < 3 && j0 < cnt) t0 = g_t2s[s0 * NCP + c];
                if (s < 3 && j1 < cnt) t1 = g_t2s[s1 * NCP + c];
                acc += t0;
                accB += t1;
            }
            for (; jj < iters; jj++) {
                int j = jj * 3 + s;
                int src = __shfl_sync(FULL, m, j < 31 ? j : 31);
                if (s < 3 && j < cnt) acc += g_t2s[src * NCP + c];
            }
        }
        acc += accB;
        float a1 = __shfl_sync(FULL, acc, (lane + 10) & 31);
        float a2 = __shfl_sync(FULL, acc, (lane + 20) & 31);
        float v = 0.0f;
        if (lane < 10) {
            float dd = g_dinv[d];
            v = dd * (acc + a1 + a2 + g_t2s[d * NCP + lane]) + b2[lane];
        }
        float mv = (lane < 10) ? v : -1e30f;
        #pragma unroll
        for (int o = 16; o; o >>= 1) mv = fmaxf(mv, __shfl_xor_sync(FULL, mv, o));
        float ex = (lane < 10) ? expf(v - mv) : 0.0f;
        float sm = ex;
        #pragma unroll
        for (int o = 16; o; o >>= 1) sm += __shfl_xor_sync(FULL, sm, o);
        float lse = mv + logf(sm);
        if (lane < 10) atomicAdd(&sacc[lane], v - lse);
    }
    __syncthreads();
    if (tid < NCLS) atomicAdd(&out[tid], sacc[tid] * (1.0f / (float)NN));
}

// ---------------- launch ----------------
extern "C" void kernel_launch(void* const* d_in, const int* in_sizes, int n_in,
                              void* d_out, int out_size) {
    const float* x  = (const float*)d_in[0];
    const void*  ei = d_in[1];
    const float* W1 = (const float*)d_in[2];
    const float* b1 = (const float*)d_in[3];
    const float* W2 = (const float*)d_in[4];
    const float* b2 = (const float*)d_in[5];
    float* out = (float*)d_out;

    k_degree   <<<(NE + 255) / 256, 256>>>(ei);            // 0
    k_scan     <<<NBS, SB>>>(out);                         // 1
    k_fillx    <<<(NN * 32 + 255) / 256, 256>>>(ei, x);    // 2
    k_gather1  <<<(NN * 32 + 255) / 256, 256>>>();         // 3  <- profiled
    k_gemm12   <<<(NN + 63) / 64, 256>>>(W1, b1, W2);      // 4
    k_gather2f <<<(NN * 32 + 511) / 512, 512>>>(b2, out);  // 5
}

// round 15
// speedup vs baseline: 1.0217x; 1.0217x over previous
#include <cuda_runtime.h>
#include <cuda_fp16.h>
#include <math.h>

#define NN   100000
#define NE   1600000
#define INF  64
#define HIDD 128
#define NCLS 10
#define NCP  12
#define SB   512
#define NBS  ((NN + SB - 1) / SB)    // 196 scan blocks
#define FULL 0xffffffffu

// packed f32x2 helpers
__device__ __forceinline__ unsigned long long f2pk(float lo, float hi) {
    unsigned long long r;
    asm("mov.b64 %0, {%1, %2};" : "=l"(r) : "f"(lo), "f"(hi));
    return r;
}
__device__ __forceinline__ void ffma2(unsigned long long& d,
                                      unsigned long long a,
                                      unsigned long long b) {
    asm("fma.rn.f32x2 %0, %1, %2, %0;" : "+l"(d) : "l"(a), "l"(b));
}
__device__ __forceinline__ float2 f2unpk(unsigned long long v) {
    float lo, hi;
    asm("mov.b64 {%0, %1}, %2;" : "=f"(lo), "=f"(hi) : "l"(v));
    return make_float2(lo, hi);
}

// per-warp dtype sniff: int64 edge_index => odd 32-bit words of first 32 elems all 0
__device__ __forceinline__ bool sniff_is64(const void* ei_raw, int lane) {
    unsigned int odd = ((const unsigned int*)ei_raw)[lane * 2 + 1];
    return __ballot_sync(FULL, odd != 0u) == 0u;
}

// ---------------- scratch (no allocations allowed) ----------------
// Pipeline is self-restoring: g_cnt and g_done return to 0 by the end of every
// kernel_launch invocation (module-load state is zero), so no init pass.
__device__ int   g_done;
__device__ int   g_cnt[NN];
__device__ int   g_offs[NN];          // block-local exclusive scan (SB-wide blocks)
__device__ int   g_bsum[NBS];
__device__ int   g_bpre[NBS];
__device__ float g_dinv[NN];
__device__ unsigned short g_rank[NE]; // 3.2 MB : edge's rank within its dest bucket
__device__ int   g_msrc[NE];          // 6.4 MB : CSR src per slot
__device__ __half2 g_xh[NN * 32];     // 12.8 MB : xs = dinv*x in half
__device__ float4 g_agg1[NN * (INF / 4)];   // 25.6 MB
__device__ float g_t2s[NN * NCP];           // 4.8 MB : dinv*(h@W2), stride 12

// ---------------- kernels ----------------

// degree histogram + rank ticket (returning atomic; rank = position in bucket)
__global__ void k_degree(const void* __restrict__ ei_raw) {
    int e = blockIdx.x * blockDim.x + threadIdx.x;
    bool is64 = sniff_is64(ei_raw, threadIdx.x & 31);
    if (e >= NE) return;
    int c;
    if (is64) c = (int)((const long long*)ei_raw)[NE + e];
    else      c = ((const int*)ei_raw)[NE + e];
    c = min(max(c, 0), NN - 1);
    int t = atomicAdd(&g_cnt[c], 1);
    g_rank[e] = (unsigned short)t;
}

// fused scan: block-local exclusive scan + dinv + out-zero; last block scans
// block sums and self-resets g_done
__global__ void k_scan(float* __restrict__ out) {
    __shared__ int s[SB];
    __shared__ int isLast;
    int tid = threadIdx.x;
    int i = blockIdx.x * SB + tid;
    if (blockIdx.x == 0 && tid < NCLS) out[tid] = 0.0f;
    int v = (i < NN) ? g_cnt[i] : 0;
    if (i < NN) g_dinv[i] = rsqrtf((float)(v + 1));
    s[tid] = v;
    __syncthreads();
    #pragma unroll
    for (int st = 1; st < SB; st <<= 1) {
        int t = (tid >= st) ? s[tid - st] : 0;
        __syncthreads();
        s[tid] += t;
        __syncthreads();
    }
    if (i < NN) g_offs[i] = s[tid] - v;
    if (tid == SB - 1) {
        g_bsum[blockIdx.x] = s[SB - 1];
        __threadfence();
        int t = atomicAdd(&g_done, 1);
        isLast = (t == (int)gridDim.x - 1);
    }
    __syncthreads();
    if (isLast) {
        int v2 = (tid < NBS) ? g_bsum[tid] : 0;
        s[tid] = v2;
        __syncthreads();
        #pragma unroll
        for (int st = 1; st < SB; st <<= 1) {
            int t = (tid >= st) ? s[tid - st] : 0;
            __syncthreads();
            s[tid] += t;
            __syncthreads();
        }
        if (tid < NBS) g_bpre[tid] = s[tid] - v2;
        if (tid == 0) g_done = 0;        // self-restore for next replay
    }
}

// fused: CSR fill via precomputed rank (NO atomics) + xs = dinv*x -> half
__global__ void k_fillx(const void* __restrict__ ei_raw, const float* __restrict__ x) {
    int i = blockIdx.x * blockDim.x + threadIdx.x;   // NN*32 = 3.2M threads
    bool is64 = sniff_is64(ei_raw, threadIdx.x & 31);
    if (i < NE) {
        int r, c;
        if (is64) {
            const long long* ei = (const long long*)ei_raw;
            r = (int)ei[i];  c = (int)ei[NE + i];
        } else {
            const int* ei = (const int*)ei_raw;
            r = ei[i];       c = ei[NE + i];
        }
        r = min(max(r, 0), NN - 1);
        c = min(max(c, 0), NN - 1);
        int pos = g_offs[c] + g_bpre[c >> 9] + (int)g_rank[i];
        g_msrc[pos] = r;
    }
    if (i < NN * 32) {
        int node = i >> 5;
        float d = g_dinv[node];
        float2 v = ((const float2*)x)[i];
        g_xh[i] = __floats2half2_rn(d * v.x, d * v.y);
    }
}

// layer-1 aggregation: warp per dest node.
// Inner loop minimized: pre-scaled indices shfl'd, HADD2 pair-combine, float acc.
__global__ void k_gather1() {
    int wid  = (blockIdx.x * blockDim.x + threadIdx.x) >> 5;
    int lane = threadIdx.x & 31;
    if (wid >= NN) return;
    int d = wid;
    float2 acc = __half22float2(g_xh[d * 32 + lane]);   // self term xs[d]
    float2 acc2 = make_float2(0.f, 0.f);
    int beg = g_offs[d] + g_bpre[d >> 9];
    int deg = g_cnt[d];
    for (int base = 0; base < deg; base += 32) {
        int rem = deg - base;
        int cnt = rem < 32 ? rem : 32;
        int m = (lane < cnt) ? (g_msrc[beg + base + lane] << 5) : 0;  // pre-scaled
        int j = 0;
        for (; j + 4 <= cnt; j += 4) {
            int s0 = __shfl_sync(FULL, m, j);
            int s1 = __shfl_sync(FULL, m, j + 1);
            int s2 = __shfl_sync(FULL, m, j + 2);
            int s3 = __shfl_sync(FULL, m, j + 3);
            __half2 v0 = g_xh[s0 + lane];
            __half2 v1 = g_xh[s1 + lane];
            __half2 v2 = g_xh[s2 + lane];
            __half2 v3 = g_xh[s3 + lane];
            float2 f01 = __half22float2(__hadd2(v0, v1));   // pairwise in half
            float2 f23 = __half22float2(__hadd2(v2, v3));
            acc.x  += f01.x;  acc.y  += f01.y;
            acc2.x += f23.x;  acc2.y += f23.y;
        }
        for (; j < cnt; j++) {
            int src = __shfl_sync(FULL, m, j);
            float2 v = __half22float2(g_xh[src + lane]);
            acc.x += v.x;  acc.y += v.y;
        }
    }
    float dd = g_dinv[d];
    acc.x = (acc.x + acc2.x) * dd;
    acc.y = (acc.y + acc2.y) * dd;
    ((float2*)g_agg1)[d * 32 + lane] = acc;
}

// fused: h = relu(agg1@W1 + b1) [smem only] ; t2s = dinv*(h@W2)
__global__ void k_gemm12(const float* __restrict__ W1, const float* __restrict__ b1,
                         const float* __restrict__ W2) {
    __shared__ float As[64 * 64];        // A tile / then W2 (1280 floats)
    __shared__ float Bs[64 * 132];       // W1 (64x128) / then h tile stride 132
    int tid = threadIdx.x;
    int bnode = blockIdx.x * 64;

    for (int t = tid; t < (64 * 128) / 4; t += 256)
        ((float4*)Bs)[t] = ((const float4*)W1)[t];
    for (int t = tid; t < 64 * 16; t += 256) {
        int lr = t >> 4, q = t & 15;
        int node = bnode + lr;
        float4 v = (node < NN) ? g_agg1[node * 16 + q]
                               : make_float4(0.f, 0.f, 0.f, 0.f);
        ((float4*)As)[t] = v;
    }
    __syncthreads();

    int tx = tid & 31, ty = tid >> 5;
    unsigned long long a01[8], a23[8];
    #pragma unroll
    for (int i = 0; i < 8; i++) { a01[i] = 0ull; a23[i] = 0ull; }

    #pragma unroll 4
    for (int k = 0; k < 64; k++) {
        float4 bb = ((const float4*)Bs)[k * 32 + tx];
        unsigned long long b01 = f2pk(bb.x, bb.y);
        unsigned long long b23 = f2pk(bb.z, bb.w);
        #pragma unroll
        for (int i = 0; i < 8; i++) {
            float a = As[(ty * 8 + i) * 64 + k];
            unsigned long long aa = f2pk(a, a);
            ffma2(a01[i], aa, b01);
            ffma2(a23[i], aa, b23);
        }
    }
    __syncthreads();

    float4 bias = ((const float4*)b1)[tx];
    #pragma unroll
    for (int i = 0; i < 8; i++) {
        float2 p = f2unpk(a01[i]);
        float2 q = f2unpk(a23[i]);
        float* hrow = &Bs[(ty * 8 + i) * 132 + tx * 4];
        hrow[0] = fmaxf(p.x + bias.x, 0.0f);
        hrow[1] = fmaxf(p.y + bias.y, 0.0f);
        hrow[2] = fmaxf(q.x + bias.z, 0.0f);
        hrow[3] = fmaxf(q.y + bias.w, 0.0f);
    }
    for (int t = tid; t < HIDD * NCLS; t += 256) As[t] = W2[t];
    __syncthreads();

    for (int o = tid; o < 64 * NCLS; o += 256) {
        int ln = o / NCLS, c = o - ln * NCLS;
        int node = bnode + ln;
        if (node < NN) {
            const float* h = &Bs[ln * 132];
            float s = 0.0f;
            #pragma unroll 8
            for (int k = 0; k < HIDD; k++) s = fmaf(h[k], As[k * NCLS + c], s);
            g_t2s[node * NCP + c] = g_dinv[node] * s;
        }
    }
}

// fused: layer-2 gather + bias + self + log_softmax + global mean-reduce.
// Also self-restores g_cnt to 0 (so no init pass is needed next replay).
__global__ void k_gather2f(const float* __restrict__ b2, float* __restrict__ out) {
    __shared__ float sacc[NCLS];
    int tid = threadIdx.x;
    if (tid < NCLS) sacc[tid] = 0.0f;
    __syncthreads();
    int wid  = (blockIdx.x * blockDim.x + tid) >> 5;
    int lane = tid & 31;
    if (wid < NN) {
        int d = wid;
        int s = lane / 10;          // 0..2 active
        int c = lane - s * 10;
        float acc = 0.0f, accB = 0.0f;
        int beg = g_offs[d] + g_bpre[d >> 9];
        int deg = g_cnt[d];
        if (lane == 0) g_cnt[d] = 0;     // self-restore after last read
        for (int base = 0; base < deg; base += 32) {
            int rem = deg - base;
            int cnt = rem < 32 ? rem : 32;
            int m = (lane < cnt) ? g_msrc[beg + base + lane] : 0;
            int iters = (cnt + 2) / 3;
            int jj = 0;
            for (; jj + 2 <= iters; jj += 2) {
                int j0 = jj * 3 + s;
                int j1 = j0 + 3;
                int s0 = __shfl_sync(FULL, m, j0 < 31 ? j0 : 31);
                int s1 = __shfl_sync(FULL, m, j1 < 31 ? j1 : 31);
                float t0 = 0.f, t1 = 0.f;
                if (s < 3 && j0 < cnt) t0 = g_t2s[s0 * NCP + c];
                if (s < 3 && j1 < cnt) t1 = g_t2s[s1 * NCP + c];
                acc += t0;
                accB += t1;
            }
            for (; jj < iters; jj++) {
                int j = jj * 3 + s;
                int src = __shfl_sync(FULL, m, j < 31 ? j : 31);
                if (s < 3 && j < cnt) acc += g_t2s[src * NCP + c];
            }
        }
        acc += accB;
        float a1 = __shfl_sync(FULL, acc, (lane + 10) & 31);
        float a2 = __shfl_sync(FULL, acc, (lane + 20) & 31);
        float v = 0.0f;
        if (lane < 10) {
            float dd = g_dinv[d];
            v = dd * (acc + a1 + a2 + g_t2s[d * NCP + lane]) + b2[lane];
        }
        float mv = (lane < 10) ? v : -1e30f;
        #pragma unroll
        for (int o = 16; o; o >>= 1) mv = fmaxf(mv, __shfl_xor_sync(FULL, mv, o));
        float ex = (lane < 10) ? expf(v - mv) : 0.0f;
        float sm = ex;
        #pragma unroll
        for (int o = 16; o; o >>= 1) sm += __shfl_xor_sync(FULL, sm, o);
        float lse = mv + logf(sm);
        if (lane < 10) atomicAdd(&sacc[lane], v - lse);
    }
    __syncthreads();
    if (tid < NCLS) atomicAdd(&out[tid], sacc[tid] * (1.0f / (float)NN));
}

// ---------------- launch ----------------
extern "C" void kernel_launch(void* const* d_in, const int* in_sizes, int n_in,
                              void* d_out, int out_size) {
    const float* x  = (const float*)d_in[0];
    const void*  ei = d_in[1];
    const float* W1 = (const float*)d_in[2];
    const float* b1 = (const float*)d_in[3];
    const float* W2 = (const float*)d_in[4];
    const float* b2 = (const float*)d_in[5];
    float* out = (float*)d_out;

    k_degree   <<<(NE + 255) / 256, 256>>>(ei);            // 0
    k_scan     <<<NBS, SB>>>(out);                         // 1
    k_fillx    <<<(NN * 32 + 255) / 256, 256>>>(ei, x);    // 2
    k_gather1  <<<(NN * 32 + 255) / 256, 256>>>();         // 3  <- profiled
    k_gemm12   <<<(NN + 63) / 64, 256>>>(W1, b1, W2);      // 4
    k_gather2f <<<(NN * 32 + 511) / 512, 512>>>(b2, out);  // 5
}

// round 16
// speedup vs baseline: 1.0272x; 1.0054x over previous
#include <cuda_runtime.h>
#include <cuda_fp16.h>
#include <math.h>

#define NN   100000
#define NE   1600000
#define INF  64
#define HIDD 128
#define NCLS 10
#define NCP  12
#define SB   512
#define NBS  ((NN + SB - 1) / SB)    // 196 scan blocks
#define FULL 0xffffffffu

// packed f32x2 helpers
__device__ __forceinline__ unsigned long long f2pk(float lo, float hi) {
    unsigned long long r;
    asm("mov.b64 %0, {%1, %2};" : "=l"(r) : "f"(lo), "f"(hi));
    return r;
}
__device__ __forceinline__ void ffma2(unsigned long long& d,
                                      unsigned long long a,
                                      unsigned long long b) {
    asm("fma.rn.f32x2 %0, %1, %2, %0;" : "+l"(d) : "l"(a), "l"(b));
}
__device__ __forceinline__ float2 f2unpk(unsigned long long v) {
    float lo, hi;
    asm("mov.b64 {%0, %1}, %2;" : "=f"(lo), "=f"(hi) : "l"(v));
    return make_float2(lo, hi);
}

// per-warp dtype sniff: int64 edge_index => odd 32-bit words of first 32 elems all 0
__device__ __forceinline__ bool sniff_is64(const void* ei_raw, int lane) {
    unsigned int odd = ((const unsigned int*)ei_raw)[lane * 2 + 1];
    return __ballot_sync(FULL, odd != 0u) == 0u;
}

// ---------------- scratch (no allocations allowed) ----------------
// Pipeline is self-restoring: g_cnt and g_done return to 0 by the end of every
// kernel_launch invocation (module-load state is zero), so no init pass.
__device__ int   g_done;
__device__ int   g_cnt[NN];
__device__ int   g_offs[NN];          // block-local exclusive scan (SB-wide blocks)
__device__ int   g_bsum[NBS];
__device__ int   g_bpre[NBS];
__device__ float g_dinv[NN];
__device__ unsigned short g_rank[NE]; // 3.2 MB : edge's rank within its dest bucket
__device__ int   g_msrc[NE];          // 6.4 MB : CSR src per slot
__device__ __half2 g_xh[NN * 32];     // 12.8 MB : xs = dinv*x in half
__device__ float4 g_agg1[NN * (INF / 4)];   // 25.6 MB
__device__ float g_t2s[NN * NCP];           // 4.8 MB : dinv*(h@W2), stride 12

// ---------------- kernels ----------------

// degree histogram + rank ticket (returning atomic; rank = position in bucket)
__global__ void k_degree(const void* __restrict__ ei_raw) {
    int e = blockIdx.x * blockDim.x + threadIdx.x;
    bool is64 = sniff_is64(ei_raw, threadIdx.x & 31);
    if (e >= NE) return;
    int c;
    if (is64) c = (int)((const long long*)ei_raw)[NE + e];
    else      c = ((const int*)ei_raw)[NE + e];
    c = min(max(c, 0), NN - 1);
    int t = atomicAdd(&g_cnt[c], 1);
    g_rank[e] = (unsigned short)t;
}

// fused scan: block-local exclusive scan + dinv + out-zero; last block scans
// block sums and self-resets g_done
__global__ void k_scan(float* __restrict__ out) {
    __shared__ int s[SB];
    __shared__ int isLast;
    int tid = threadIdx.x;
    int i = blockIdx.x * SB + tid;
    if (blockIdx.x == 0 && tid < NCLS) out[tid] = 0.0f;
    int v = (i < NN) ? g_cnt[i] : 0;
    if (i < NN) g_dinv[i] = rsqrtf((float)(v + 1));
    s[tid] = v;
    __syncthreads();
    #pragma unroll
    for (int st = 1; st < SB; st <<= 1) {
        int t = (tid >= st) ? s[tid - st] : 0;
        __syncthreads();
        s[tid] += t;
        __syncthreads();
    }
    if (i < NN) g_offs[i] = s[tid] - v;
    if (tid == SB - 1) {
        g_bsum[blockIdx.x] = s[SB - 1];
        __threadfence();
        int t = atomicAdd(&g_done, 1);
        isLast = (t == (int)gridDim.x - 1);
    }
    __syncthreads();
    if (isLast) {
        int v2 = (tid < NBS) ? g_bsum[tid] : 0;
        s[tid] = v2;
        __syncthreads();
        #pragma unroll
        for (int st = 1; st < SB; st <<= 1) {
            int t = (tid >= st) ? s[tid - st] : 0;
            __syncthreads();
            s[tid] += t;
            __syncthreads();
        }
        if (tid < NBS) g_bpre[tid] = s[tid] - v2;
        if (tid == 0) g_done = 0;        // self-restore for next replay
    }
}

// fused: CSR fill via precomputed rank (NO atomics) + xs = dinv*x -> half
__global__ void k_fillx(const void* __restrict__ ei_raw, const float* __restrict__ x) {
    int i = blockIdx.x * blockDim.x + threadIdx.x;   // NN*32 = 3.2M threads
    bool is64 = sniff_is64(ei_raw, threadIdx.x & 31);
    if (i < NE) {
        int r, c;
        if (is64) {
            const long long* ei = (const long long*)ei_raw;
            r = (int)ei[i];  c = (int)ei[NE + i];
        } else {
            const int* ei = (const int*)ei_raw;
            r = ei[i];       c = ei[NE + i];
        }
        r = min(max(r, 0), NN - 1);
        c = min(max(c, 0), NN - 1);
        int pos = g_offs[c] + g_bpre[c >> 9] + (int)g_rank[i];
        g_msrc[pos] = r;
    }
    if (i < NN * 32) {
        int node = i >> 5;
        float d = g_dinv[node];
        float2 v = ((const float2*)x)[i];
        g_xh[i] = __floats2half2_rn(d * v.x, d * v.y);
    }
}

// layer-1 aggregation: warp per dest node; 8 lanes per edge, 4 edges in flight.
// Per 4 edges per lane: 1 shfl + 1 LDG.128 + 4 HADD2. half2 accumulate (<=12 adds),
// one-time fp32 cross-group reduce + exact self term.
__global__ void k_gather1() {
    int wid  = (blockIdx.x * blockDim.x + threadIdx.x) >> 5;
    int lane = threadIdx.x & 31;
    if (wid >= NN) return;
    int d = wid;
    int g = lane >> 3;            // edge group 0..3
    int l = lane & 7;             // feature octet: features 8l .. 8l+7
    __half2 h0 = __float2half2_rn(0.f), h1 = h0, h2 = h0, h3 = h0;
    int beg = g_offs[d] + g_bpre[d >> 9];
    int deg = g_cnt[d];
    for (int base = 0; base < deg; base += 32) {
        int rem = deg - base;
        int cnt = rem < 32 ? rem : 32;
        int m = (lane < cnt) ? (g_msrc[beg + base + lane] << 5) : 0;  // half2 units
        for (int j = 0; j < cnt; j += 4) {
            int e = j + g;
            int s = __shfl_sync(FULL, m, e & 31);
            if (e < cnt) {
                uint4 u = *(const uint4*)&g_xh[s + l * 4];   // 16B of edge's row
                h0 = __hadd2(h0, *reinterpret_cast<__half2*>(&u.x));
                h1 = __hadd2(h1, *reinterpret_cast<__half2*>(&u.y));
                h2 = __hadd2(h2, *reinterpret_cast<__half2*>(&u.z));
                h3 = __hadd2(h3, *reinterpret_cast<__half2*>(&u.w));
            }
        }
    }
    // fp32 cross-group reduction (lanes sharing l combine over g)
    float2 f0 = __half22float2(h0);
    float2 f1 = __half22float2(h1);
    float2 f2 = __half22float2(h2);
    float2 f3 = __half22float2(h3);
    #pragma unroll
    for (int off = 8; off <= 16; off <<= 1) {
        f0.x += __shfl_xor_sync(FULL, f0.x, off);
        f0.y += __shfl_xor_sync(FULL, f0.y, off);
        f1.x += __shfl_xor_sync(FULL, f1.x, off);
        f1.y += __shfl_xor_sync(FULL, f1.y, off);
        f2.x += __shfl_xor_sync(FULL, f2.x, off);
        f2.y += __shfl_xor_sync(FULL, f2.y, off);
        f3.x += __shfl_xor_sync(FULL, f3.x, off);
        f3.y += __shfl_xor_sync(FULL, f3.y, off);
    }
    if (g == 0) {
        float dd = g_dinv[d];
        uint4 u = *(const uint4*)&g_xh[d * 32 + l * 4];      // self xs (exact add)
        float2 s0 = __half22float2(*reinterpret_cast<__half2*>(&u.x));
        float2 s1 = __half22float2(*reinterpret_cast<__half2*>(&u.y));
        float2 s2 = __half22float2(*reinterpret_cast<__half2*>(&u.z));
        float2 s3 = __half22float2(*reinterpret_cast<__half2*>(&u.w));
        float4 o0, o1;
        o0.x = (f0.x + s0.x) * dd;  o0.y = (f0.y + s0.y) * dd;
        o0.z = (f1.x + s1.x) * dd;  o0.w = (f1.y + s1.y) * dd;
        o1.x = (f2.x + s2.x) * dd;  o1.y = (f2.y + s2.y) * dd;
        o1.z = (f3.x + s3.x) * dd;  o1.w = (f3.y + s3.y) * dd;
        g_agg1[d * 16 + l * 2]     = o0;
        g_agg1[d * 16 + l * 2 + 1] = o1;
    }
}

// fused: h = relu(agg1@W1 + b1) [smem only] ; t2s = dinv*(h@W2)
__global__ void k_gemm12(const float* __restrict__ W1, const float* __restrict__ b1,
                         const float* __restrict__ W2) {
    __shared__ float As[64 * 64];        // A tile / then W2 (1280 floats)
    __shared__ float Bs[64 * 132];       // W1 (64x128) / then h tile stride 132
    int tid = threadIdx.x;
    int bnode = blockIdx.x * 64;

    for (int t = tid; t < (64 * 128) / 4; t += 256)
        ((float4*)Bs)[t] = ((const float4*)W1)[t];
    for (int t = tid; t < 64 * 16; t += 256) {
        int lr = t >> 4, q = t & 15;
        int node = bnode + lr;
        float4 v = (node < NN) ? g_agg1[node * 16 + q]
                               : make_float4(0.f, 0.f, 0.f, 0.f);
        ((float4*)As)[t] = v;
    }
    __syncthreads();

    int tx = tid & 31, ty = tid >> 5;
    unsigned long long a01[8], a23[8];
    #pragma unroll
    for (int i = 0; i < 8; i++) { a01[i] = 0ull; a23[i] = 0ull; }

    #pragma unroll 4
    for (int k = 0; k < 64; k++) {
        float4 bb = ((const float4*)Bs)[k * 32 + tx];
        unsigned long long b01 = f2pk(bb.x, bb.y);
        unsigned long long b23 = f2pk(bb.z, bb.w);
        #pragma unroll
        for (int i = 0; i < 8; i++) {
            float a = As[(ty * 8 + i) * 64 + k];
            unsigned long long aa = f2pk(a, a);
            ffma2(a01[i], aa, b01);
            ffma2(a23[i], aa, b23);
        }
    }
    __syncthreads();

    float4 bias = ((const float4*)b1)[tx];
    #pragma unroll
    for (int i = 0; i < 8; i++) {
        float2 p = f2unpk(a01[i]);
        float2 q = f2unpk(a23[i]);
        float* hrow = &Bs[(ty * 8 + i) * 132 + tx * 4];
        hrow[0] = fmaxf(p.x + bias.x, 0.0f);
        hrow[1] = fmaxf(p.y + bias.y, 0.0f);
        hrow[2] = fmaxf(q.x + bias.z, 0.0f);
        hrow[3] = fmaxf(q.y + bias.w, 0.0f);
    }
    for (int t = tid; t < HIDD * NCLS; t += 256) As[t] = W2[t];
    __syncthreads();

    for (int o = tid; o < 64 * NCLS; o += 256) {
        int ln = o / NCLS, c = o - ln * NCLS;
        int node = bnode + ln;
        if (node < NN) {
            const float* h = &Bs[ln * 132];
            float s = 0.0f;
            #pragma unroll 8
            for (int k = 0; k < HIDD; k++) s = fmaf(h[k], As[k * NCLS + c], s);
            g_t2s[node * NCP + c] = g_dinv[node] * s;
        }
    }
}

// fused: layer-2 gather + bias + self + log_softmax + global mean-reduce.
// Also self-restores g_cnt to 0 (so no init pass is needed next replay).
__global__ void k_gather2f(const float* __restrict__ b2, float* __restrict__ out) {
    __shared__ float sacc[NCLS];
    int tid = threadIdx.x;
    if (tid < NCLS) sacc[tid] = 0.0f;
    __syncthreads();
    int wid  = (blockIdx.x * blockDim.x + tid) >> 5;
    int lane = tid & 31;
    if (wid < NN) {
        int d = wid;
        int s = lane / 10;          // 0..2 active
        int c = lane - s * 10;
        float acc = 0.0f, accB = 0.0f;
        int beg = g_offs[d] + g_bpre[d >> 9];
        int deg = g_cnt[d];
        if (lane == 0) g_cnt[d] = 0;     // self-restore after last read
        for (int base = 0; base < deg; base += 32) {
            int rem = deg - base;
            int cnt = rem < 32 ? rem : 32;
            int m = (lane < cnt) ? g_msrc[beg + base + lane] : 0;
            int iters = (cnt + 2) / 3;
            int jj = 0;
            for (; jj + 2 <= iters; jj += 2) {
                int j0 = jj * 3 + s;
                int j1 = j0 + 3;
                int s0 = __shfl_sync(FULL, m, j0 < 31 ? j0 : 31);
                int s1 = __shfl_sync(FULL, m, j1 < 31 ? j1 : 31);
                float t0 = 0.f, t1 = 0.f;
                if (s < 3 && j0 < cnt) t0 = g_t2s[s0 * NCP + c];
                if (s < 3 && j1 < cnt) t1 = g_t2s[s1 * NCP + c];
                acc += t0;
                accB += t1;
            }
            for (; jj < iters; jj++) {
                int j = jj * 3 + s;
                int src = __shfl_sync(FULL, m, j < 31 ? j : 31);
                if (s < 3 && j < cnt) acc += g_t2s[src * NCP + c];
            }
        }
        acc += accB;
        float a1 = __shfl_sync(FULL, acc, (lane + 10) & 31);
        float a2 = __shfl_sync(FULL, acc, (lane + 20) & 31);
        float v = 0.0f;
        if (lane < 10) {
            float dd = g_dinv[d];
            v = dd * (acc + a1 + a2 + g_t2s[d * NCP + lane]) + b2[lane];
        }
        float mv = (lane < 10) ? v : -1e30f;
        #pragma unroll
        for (int o = 16; o; o >>= 1) mv = fmaxf(mv, __shfl_xor_sync(FULL, mv, o));
        float ex = (lane < 10) ? expf(v - mv) : 0.0f;
        float sm = ex;
        #pragma unroll
        for (int o = 16; o; o >>= 1) sm += __shfl_xor_sync(FULL, sm, o);
        float lse = mv + logf(sm);
        if (lane < 10) atomicAdd(&sacc[lane], v - lse);
    }
    __syncthreads();
    if (tid < NCLS) atomicAdd(&out[tid], sacc[tid] * (1.0f / (float)NN));
}

// ---------------- launch ----------------
extern "C" void kernel_launch(void* const* d_in, const int* in_sizes, int n_in,
                              void* d_out, int out_size) {
    const float* x  = (const float*)d_in[0];
    const void*  ei = d_in[1];
    const float* W1 = (const float*)d_in[2];
    const float* b1 = (const float*)d_in[3];
    const float* W2 = (const float*)d_in[4];
    const float* b2 = (const float*)d_in[5];
    float* out = (float*)d_out;

    k_degree   <<<(NE + 255) / 256, 256>>>(ei);            // 0
    k_scan     <<<NBS, SB>>>(out);                         // 1
    k_fillx    <<<(NN * 32 + 255) / 256, 256>>>(ei, x);    // 2
    k_gather1  <<<(NN * 32 + 255) / 256, 256>>>();         // 3  <- profiled
    k_gemm12   <<<(NN + 63) / 64, 256>>>(W1, b1, W2);      // 4
    k_gather2f <<<(NN * 32 + 511) / 512, 512>>>(b2, out);  // 5
}